// round 5
// baseline (speedup 1.0000x reference)
#include <cuda_runtime.h>
#include <math.h>
#include <stdint.h>

// ---------------- problem constants ----------------
#define NBT 512            // B*T
#define NN 64
#define DD 128
#define HH 4
#define DHH 32
#define LL 3
#define D4 512
#define NROWS (NBT*NN)     // 32768
#define MAXE 4096

// ---------------- scratch (device globals; no allocation) ----------------
__device__ float g_Z    [NROWS*DD];
__device__ float g_Hmix [NROWS*DD];
__device__ float g_Xq   [NROWS*DD];
__device__ float g_Xv   [NROWS*DD];
__device__ float g_Y    [NROWS*DD];
__device__ float g_U    [NROWS*DD];
__device__ float g_M1   [NROWS*D4];
__device__ float g_A    [NN*NN];
__device__ float g_logA0[MAXE];
__device__ int   g_rowptr[NN+1];
__device__ float g_mu1  [NROWS];
__device__ float g_rs1  [NROWS];
__device__ float g_mu2  [NROWS];
__device__ float g_rs2  [NROWS];
// LN-folded weights + epilogue vectors
__device__ float g_Wq   [DD*DD];
__device__ float g_Wv   [DD*DD];
__device__ float g_Wm1p [DD*D4];
__device__ float g_csq[DD], g_uq[DD];
__device__ float g_csv[DD], g_uv[DD];
__device__ float g_csm[D4], g_um[D4];

// ---------------- 3xTF32 tensor-core GEMM ----------------
// C = act( [LN-epi]( A@B ) + bias ) + add1 + add2
// LN-epi (if ecs): v = ers[r]*(acc - emu[r]*ecs[c]) + eu[c]   (bias folded in eu)
#define BM 128
#define BN 128
#define BKT 16
#define AST 20
#define BST 132

__device__ __forceinline__ void cp_async16(void* smem, const void* gmem) {
    unsigned sa = (unsigned)__cvta_generic_to_shared(smem);
    asm volatile("cp.async.cg.shared.global [%0], [%1], 16;\n" :: "r"(sa), "l"(gmem));
}
__device__ __forceinline__ uint32_t f2tf(float x) {
    uint32_t r; asm("cvt.rna.tf32.f32 %0, %1;" : "=r"(r) : "f"(x)); return r;
}
__device__ __forceinline__ void split2(float x, uint32_t& hi, uint32_t& lo) {
    uint32_t h = __float_as_uint(x) & 0xffffe000u;
    hi = h;
    lo = f2tf(x - __uint_as_float(h));
}
__device__ __forceinline__ void mma_tf32(float* c, const uint32_t* a, const uint32_t* b) {
    asm volatile("mma.sync.aligned.m16n8k8.row.col.f32.tf32.tf32.f32 "
        "{%0,%1,%2,%3}, {%4,%5,%6,%7}, {%8,%9}, {%0,%1,%2,%3};"
        : "+f"(c[0]), "+f"(c[1]), "+f"(c[2]), "+f"(c[3])
        : "r"(a[0]), "r"(a[1]), "r"(a[2]), "r"(a[3]), "r"(b[0]), "r"(b[1]));
}

__global__ __launch_bounds__(256) void tf32gemm_kernel(
    const float* __restrict__ A, const float* __restrict__ B, float* __restrict__ C,
    int M, int K, int N,
    const float* __restrict__ bias, const float* __restrict__ add1,
    const float* __restrict__ add2, int act,
    const float* __restrict__ emu, const float* __restrict__ ers,
    const float* __restrict__ ecs, const float* __restrict__ eu)
{
    __shared__ float As[2][BM * AST];
    __shared__ float Bs[2][BKT * BST];

    const int tid  = threadIdx.x;
    const int lane = tid & 31;
    const int wid  = tid >> 5;
    const int wm = (wid & 1) * 64;
    const int wn = (wid >> 1) * 32;
    const int bm = blockIdx.y * BM;
    const int bn = blockIdx.x * BN;

    const float* Agp = A + (size_t)bm * K;
    const float* Bgp = B + bn;

    const int arow = tid >> 1;
    const int acol = (tid & 1) * 8;
    const int bidx0 = tid * 2;

    float c[4][4][4];
    #pragma unroll
    for (int mi = 0; mi < 4; mi++)
        #pragma unroll
        for (int ni = 0; ni < 4; ni++)
            #pragma unroll
            for (int q = 0; q < 4; q++) c[mi][ni][q] = 0.f;

    const int ntiles = K / BKT;

    // prologue: stage 0
    {
        cp_async16(&As[0][arow * AST + acol],     Agp + (size_t)arow * K + acol);
        cp_async16(&As[0][arow * AST + acol + 4], Agp + (size_t)arow * K + acol + 4);
        #pragma unroll
        for (int i = 0; i < 2; i++) {
            int idx = bidx0 + i;
            int bk = idx >> 5, bn4 = (idx & 31) * 4;
            cp_async16(&Bs[0][bk * BST + bn4], Bgp + (size_t)bk * N + bn4);
        }
        asm volatile("cp.async.commit_group;\n");
    }

    for (int t = 0; t < ntiles; t++) {
        if (t + 1 < ntiles) {
            const int k0 = (t + 1) * BKT;
            const int buf = (t + 1) & 1;
            cp_async16(&As[buf][arow * AST + acol],     Agp + (size_t)arow * K + k0 + acol);
            cp_async16(&As[buf][arow * AST + acol + 4], Agp + (size_t)arow * K + k0 + acol + 4);
            #pragma unroll
            for (int i = 0; i < 2; i++) {
                int idx = bidx0 + i;
                int bk = idx >> 5, bn4 = (idx & 31) * 4;
                cp_async16(&Bs[buf][bk * BST + bn4], Bgp + (size_t)(k0 + bk) * N + bn4);
            }
            asm volatile("cp.async.commit_group;\n");
            asm volatile("cp.async.wait_group 1;\n");
        } else {
            asm volatile("cp.async.wait_group 0;\n");
        }
        __syncthreads();

        const float* as = As[t & 1];
        const float* bs = Bs[t & 1];
        #pragma unroll
        for (int ks = 0; ks < 2; ks++) {
            uint32_t ah[4][4], al[4][4], bh[4][2], bl[4][2];
            const int r0 = wm + (lane >> 2);
            const int k0 = ks * 8 + (lane & 3);
            #pragma unroll
            for (int mi = 0; mi < 4; mi++) {
                const int rb = (r0 + mi * 16) * AST;
                split2(as[rb + k0],               ah[mi][0], al[mi][0]);
                split2(as[rb + 8 * AST + k0],     ah[mi][1], al[mi][1]);
                split2(as[rb + k0 + 4],           ah[mi][2], al[mi][2]);
                split2(as[rb + 8 * AST + k0 + 4], ah[mi][3], al[mi][3]);
            }
            const int bn0 = wn + (lane >> 2);
            #pragma unroll
            for (int ni = 0; ni < 4; ni++) {
                split2(bs[k0 * BST + bn0 + ni * 8],       bh[ni][0], bl[ni][0]);
                split2(bs[(k0 + 4) * BST + bn0 + ni * 8], bh[ni][1], bl[ni][1]);
            }
            #pragma unroll
            for (int mi = 0; mi < 4; mi++)
                #pragma unroll
                for (int ni = 0; ni < 4; ni++) {
                    mma_tf32(c[mi][ni], al[mi], bh[ni]);
                    mma_tf32(c[mi][ni], ah[mi], bl[ni]);
                    mma_tf32(c[mi][ni], ah[mi], bh[ni]);
                }
        }
        __syncthreads();
    }

    // epilogue
    const bool lnepi = (ecs != nullptr);
    #pragma unroll
    for (int mi = 0; mi < 4; mi++) {
        const int r0 = bm + wm + mi * 16 + (lane >> 2);
        #pragma unroll
        for (int ni = 0; ni < 4; ni++) {
            const int cc = bn + wn + ni * 8 + 2 * (lane & 3);
            float b0 = 0.f, b1 = 0.f;
            if (bias) { b0 = bias[cc]; b1 = bias[cc + 1]; }
            float cs0 = 0.f, cs1 = 0.f, u0 = 0.f, u1 = 0.f;
            if (lnepi) { cs0 = ecs[cc]; cs1 = ecs[cc + 1]; u0 = eu[cc]; u1 = eu[cc + 1]; }
            #pragma unroll
            for (int half = 0; half < 2; half++) {
                const int r = r0 + half * 8;
                const size_t ro = (size_t)r * N + cc;
                float v0, v1;
                if (lnepi) {
                    float m = emu[r], s = ers[r];
                    v0 = s * (c[mi][ni][half * 2 + 0] - m * cs0) + u0;
                    v1 = s * (c[mi][ni][half * 2 + 1] - m * cs1) + u1;
                } else {
                    v0 = c[mi][ni][half * 2 + 0] + b0;
                    v1 = c[mi][ni][half * 2 + 1] + b1;
                }
                if (act) {
                    v0 = v0 / (1.0f + expf(-v0));
                    v1 = v1 / (1.0f + expf(-v1));
                }
                if (add1) { float2 a = *(const float2*)(add1 + ro); v0 += a.x; v1 += a.y; }
                if (add2) { float2 a = *(const float2*)(add2 + ro); v0 += a.x; v1 += a.y; }
                float2 o; o.x = v0; o.y = v1;
                *(float2*)(C + ro) = o;
            }
        }
    }
}

// ---------------- weight prep: W' = diag(g)W, cs = colsum(W'), u = b@W (+extra)
__global__ void wprep_kernel(const float* __restrict__ W, const float* __restrict__ g,
                             const float* __restrict__ b, const float* __restrict__ extra,
                             int N, float* __restrict__ Wp, float* __restrict__ cs,
                             float* __restrict__ u)
{
    const int n = blockIdx.x;      // column
    const int k = threadIdx.x;     // row (blockDim = 128 = DD)
    float w  = W[(size_t)k * N + n];
    float wp = g[k] * w;
    Wp[(size_t)k * N + n] = wp;
    float uu = b[k] * w;
    const int lane = k & 31, warp = k >> 5;
    #pragma unroll
    for (int o = 16; o; o >>= 1) {
        wp += __shfl_xor_sync(0xffffffffu, wp, o);
        uu += __shfl_xor_sync(0xffffffffu, uu, o);
    }
    __shared__ float scs[4], su[4];
    if (lane == 0) { scs[warp] = wp; su[warp] = uu; }
    __syncthreads();
    if (k == 0) {
        cs[n] = scs[0] + scs[1] + scs[2] + scs[3];
        float t = su[0] + su[1] + su[2] + su[3];
        u[n] = t + (extra ? extra[n] : 0.f);
    }
}

// ---------------- LN stats only (warp per row of 128) ----------------
__global__ void ln_stats_kernel(const float* __restrict__ X,
                                float* __restrict__ mu, float* __restrict__ rs)
{
    int r = blockIdx.x * (blockDim.x >> 5) + (threadIdx.x >> 5);
    if (r >= NROWS) return;
    int lane = threadIdx.x & 31;
    const float* x = X + (size_t)r * DD;
    float s = 0.f, ss = 0.f;
    #pragma unroll
    for (int q = 0; q < 4; q++) { float v = x[lane + 32*q]; s += v; ss += v*v; }
    #pragma unroll
    for (int o = 16; o; o >>= 1) {
        s  += __shfl_xor_sync(0xffffffffu, s,  o);
        ss += __shfl_xor_sync(0xffffffffu, ss, o);
    }
    float m   = s  * (1.f/128.f);
    float var = ss * (1.f/128.f) - m * m;
    if (lane == 0) { mu[r] = m; rs[r] = rsqrtf(var + 1e-5f); }
}

// ---------------- NodeGate: U <- U*g in place; emit LN2 stats ----------------
__global__ void gate_kernel(float* __restrict__ U,
    const float* __restrict__ g1w, const float* __restrict__ g1b,
    const float* __restrict__ g2w, const float* __restrict__ g2bp,
    float* __restrict__ mu2, float* __restrict__ rs2)
{
    int r = blockIdx.x * (blockDim.x >> 5) + (threadIdx.x >> 5);
    if (r >= NROWS) return;
    int lane = threadIdx.x & 31;
    float* u = U + (size_t)r * DD;
    float v[4], s = 0.f, ss = 0.f;
    #pragma unroll
    for (int q = 0; q < 4; q++) { v[q] = u[lane + 32*q]; s += v[q]; ss += v[q]*v[q]; }
    #pragma unroll
    for (int o = 16; o; o >>= 1) {
        s  += __shfl_xor_sync(0xffffffffu, s,  o);
        ss += __shfl_xor_sync(0xffffffffu, ss, o);
    }
    float m   = s  * (1.f/128.f);
    float var = ss * (1.f/128.f) - m * m;
    float acc = 0.f;
    #pragma unroll
    for (int q = 0; q < 4; q++) {
        int d = lane + 32*q;
        float t = m * g1w[d] + g1b[d];
        acc += (t / (1.f + expf(-t))) * g2w[d];
    }
    #pragma unroll
    for (int o = 16; o; o >>= 1) acc += __shfl_xor_sync(0xffffffffu, acc, o);
    float gate = 1.f / (1.f + expf(-(acc + g2bp[0])));
    #pragma unroll
    for (int q = 0; q < 4; q++) u[lane + 32*q] = v[q] * gate;
    if (lane == 0) {
        mu2[r] = m * gate;
        rs2[r] = rsqrtf(var * gate * gate + 1e-5f);
    }
}

// ---------------- Hmix = A @ LN1(Z)  (per bt; LN applied while staging) -------
__global__ __launch_bounds__(256) void hmix_kernel(const float* __restrict__ A,
    const float* __restrict__ Z,
    const float* __restrict__ mu, const float* __restrict__ rs,
    const float* __restrict__ lng, const float* __restrict__ lnb,
    float* __restrict__ Hmix)
{
    __shared__ float sA[NN*NN];
    __shared__ float sH[NN*DD];
    int bt = blockIdx.x;
    for (int t = threadIdx.x; t < NN*NN; t += blockDim.x) sA[t] = A[t];
    const float* Zb = Z + (size_t)bt * NN * DD;
    const int rbase = bt * NN;
    for (int t = threadIdx.x; t < NN*DD; t += blockDim.x) {
        int j = t >> 7, d = t & 127;
        sH[t] = (Zb[t] - mu[rbase + j]) * rs[rbase + j] * lng[d] + lnb[d];
    }
    __syncthreads();
    int d = threadIdx.x & 127;
    for (int i = threadIdx.x >> 7; i < NN; i += 2) {
        float acc = 0.f;
        #pragma unroll 8
        for (int j = 0; j < NN; j++) acc += sA[i*NN + j] * sH[j*DD + d];
        Hmix[((size_t)bt * NN + i) * DD + d] = acc;
    }
}

// ---------------- blended adjacency A ----------------
__global__ void adj_kernel(const float* __restrict__ A0, const float* __restrict__ P,
                           const float* __restrict__ Qm, const float* __restrict__ alphap,
                           float* __restrict__ A)
{
    int i = blockIdx.x, j = threadIdx.x;
    float a0 = A0[i*NN + j];
    float dot = 0.f;
    #pragma unroll
    for (int r = 0; r < 8; r++) dot += P[i*8 + r] * Qm[j*8 + r];
    float sp = (dot > 20.f) ? dot : log1pf(expf(dot));
    float ad = (a0 > 0.f) ? sp : 0.f;
    float a  = a0 * (1.f + alphap[0] * ad);
    __shared__ float sbuf[NN];
    sbuf[j] = a;
    __syncthreads();
    for (int st = 32; st >= 1; st >>= 1) {
        if (j < st) sbuf[j] += sbuf[j + st];
        __syncthreads();
    }
    A[i*NN + j] = a / (sbuf[0] + 1e-8f);
}

// ---------------- edge prep: CSR rowptr + logA0 ----------------
__global__ void rowptr_kernel(const int* __restrict__ src, int E, int* __restrict__ rowptr)
{
    int t = threadIdx.x;
    if (t > NN) return;
    int lo = 0, hi = E;
    while (lo < hi) { int mid = (lo + hi) >> 1; if (src[mid] < t) lo = mid + 1; else hi = mid; }
    rowptr[t] = lo;
}

__global__ void edge_kernel(const int* __restrict__ src, const int* __restrict__ dst,
                            const float* __restrict__ A0, int E, float* __restrict__ logA0)
{
    int e = blockIdx.x * blockDim.x + threadIdx.x;
    if (e < E) logA0[e] = logf(A0[src[e]*NN + dst[e]] + 1e-8f);
}

// ---------------- GATv2: block=(src node, bt); 2 warps per head split edges ---
__global__ __launch_bounds__(256) void attn_kernel(
    const float* __restrict__ Xq, const float* __restrict__ Xv,
    const float* __restrict__ a_att_l,
    const int* __restrict__ dstidx,
    const float* __restrict__ logA0, float* __restrict__ Y)
{
    const int i  = blockIdx.x;
    const int bt = blockIdx.y;
    const int wid  = threadIdx.x >> 5;
    const int lane = threadIdx.x & 31;
    const int h    = wid & 3;
    const int half = wid >> 2;

    __shared__ int   sdst[NN];
    __shared__ float slog[NN];
    __shared__ float sexp[HH][NN];
    __shared__ float sred[2][HH];
    __shared__ float syp[HH][32];

    const int e0 = g_rowptr[i];
    const int deg = g_rowptr[i + 1] - e0;
    for (int k = threadIdx.x; k < deg; k += blockDim.x) {
        sdst[k] = dstidx[e0 + k];
        slog[k] = logA0[e0 + k];
    }
    __syncthreads();

    const float a  = a_att_l[h * DHH + lane];
    const float qi = Xq[((size_t)bt * NN + i) * DD + h * DHH + lane];

    // scores: warps for same head split edges by parity
    float vmax = -1e30f;
    for (int k = half; k < deg; k += 2) {
        int j = sdst[k];
        float x = qi + Xq[((size_t)bt * NN + j) * DD + h * DHH + lane];
        x = (x > 0.f) ? x : 0.2f * x;
        float v = x * a;
        #pragma unroll
        for (int o = 16; o; o >>= 1) v += __shfl_xor_sync(0xffffffffu, v, o);
        v += slog[k];
        sexp[h][k] = v;
        vmax = fmaxf(vmax, v);
    }
    if (lane == 0) sred[half][h] = vmax;
    __syncthreads();
    vmax = fmaxf(sred[0][h], sred[1][h]);
    __syncthreads();

    // exp + denom: threads cover k = half*32 + lane (deg <= 64)
    float den = 0.f;
    {
        int k = half * 32 + lane;
        if (k < deg) {
            float ev = expf(sexp[h][k] - vmax);
            sexp[h][k] = ev;
            den += ev;
        }
    }
    #pragma unroll
    for (int o = 16; o; o >>= 1) den += __shfl_xor_sync(0xffffffffu, den, o);
    __syncthreads();
    if (lane == 0) sred[half][h] = den;
    __syncthreads();
    const float inv = 1.f / (sred[0][h] + sred[1][h]);

    // apply: split edges by parity, combine halves through smem
    float y = 0.f;
    for (int k = half; k < deg; k += 2) {
        int j = sdst[k];
        y += sexp[h][k] * Xv[((size_t)bt * NN + j) * DD + h * DHH + lane];
    }
    if (half == 1) syp[h][lane] = y;
    __syncthreads();
    if (half == 0)
        Y[((size_t)bt * NN + i) * DD + h * DHH + lane] = (y + syp[h][lane]) * inv;
}

// ---------------- outputs ----------------
__global__ void copy_kernel(const float* __restrict__ src, float* __restrict__ dst, int n4)
{
    int i = blockIdx.x * blockDim.x + threadIdx.x;
    if (i < n4) ((float4*)dst)[i] = ((const float4*)src)[i];
}

__global__ void s_kernel(const float* __restrict__ Z, float* __restrict__ S)
{
    int idx = blockIdx.x * blockDim.x + threadIdx.x;
    if (idx >= NBT * DD) return;
    int bt = idx >> 7, d = idx & 127;
    float acc = 0.f;
    for (int n = 0; n < NN; n++) acc += Z[(((size_t)bt * NN) + n) * DD + d];
    S[idx] = acc * (1.f / (float)NN);
}

__global__ void fill0_kernel(float* __restrict__ p, int n)
{
    int i = blockIdx.x * blockDim.x + threadIdx.x;
    if (i < n) p[i] = 0.f;
}

// ---------------- host driver ----------------
static inline void gemm(const float* A, const float* B, float* C, int M, int K, int N,
                        const float* bias, const float* add1, const float* add2, int act,
                        const float* emu = nullptr, const float* ers = nullptr,
                        const float* ecs = nullptr, const float* eu = nullptr)
{
    dim3 g(N / BN, M / BM);
    tf32gemm_kernel<<<g, 256>>>(A, B, C, M, K, N, bias, add1, add2, act,
                                emu, ers, ecs, eu);
}

extern "C" void kernel_launch(void* const* d_in, const int* in_sizes, int n_in,
                              void* d_out, int out_size)
{
    const float* X     = (const float*)d_in[0];
    const float* Wp    = (const float*)d_in[1];
    const float* bp    = (const float*)d_in[2];
    const float* P     = (const float*)d_in[3];
    const float* Qm    = (const float*)d_in[4];
    const float* alpha = (const float*)d_in[5];
    const float* ln1g  = (const float*)d_in[6];
    const float* ln1b  = (const float*)d_in[7];
    const float* Wlin  = (const float*)d_in[8];
    const float* Wval  = (const float*)d_in[9];
    const float* a_att = (const float*)d_in[10];
    const float* Wout  = (const float*)d_in[11];
    const float* g1w   = (const float*)d_in[12];
    const float* g1b   = (const float*)d_in[13];
    const float* g2w   = (const float*)d_in[14];
    const float* g2b   = (const float*)d_in[15];
    const float* ln2g  = (const float*)d_in[16];
    const float* ln2b  = (const float*)d_in[17];
    const float* Wm1   = (const float*)d_in[18];
    const float* bm1   = (const float*)d_in[19];
    const float* Wm2   = (const float*)d_in[20];
    const float* bm2   = (const float*)d_in[21];
    const float* A0    = (const float*)d_in[22];
    const int*   srcI  = (const int*)d_in[24];
    const int*   dstI  = (const int*)d_in[25];
    int E = in_sizes[24];
    float* out = (float*)d_out;

    float *Z, *Hmix, *Xq, *Xv, *Y, *U, *M1, *A, *logA0;
    float *mu1, *rs1, *mu2, *rs2;
    float *Wq, *Wv, *Wm1p, *csq, *uq, *csv, *uv, *csm, *um;
    int* rowptr;
    cudaGetSymbolAddress((void**)&Z,     g_Z);
    cudaGetSymbolAddress((void**)&Hmix,  g_Hmix);
    cudaGetSymbolAddress((void**)&Xq,    g_Xq);
    cudaGetSymbolAddress((void**)&Xv,    g_Xv);
    cudaGetSymbolAddress((void**)&Y,     g_Y);
    cudaGetSymbolAddress((void**)&U,     g_U);
    cudaGetSymbolAddress((void**)&M1,    g_M1);
    cudaGetSymbolAddress((void**)&A,     g_A);
    cudaGetSymbolAddress((void**)&logA0, g_logA0);
    cudaGetSymbolAddress((void**)&rowptr, g_rowptr);
    cudaGetSymbolAddress((void**)&mu1,   g_mu1);
    cudaGetSymbolAddress((void**)&rs1,   g_rs1);
    cudaGetSymbolAddress((void**)&mu2,   g_mu2);
    cudaGetSymbolAddress((void**)&rs2,   g_rs2);
    cudaGetSymbolAddress((void**)&Wq,    g_Wq);
    cudaGetSymbolAddress((void**)&Wv,    g_Wv);
    cudaGetSymbolAddress((void**)&Wm1p,  g_Wm1p);
    cudaGetSymbolAddress((void**)&csq,   g_csq);
    cudaGetSymbolAddress((void**)&uq,    g_uq);
    cudaGetSymbolAddress((void**)&csv,   g_csv);
    cudaGetSymbolAddress((void**)&uv,    g_uv);
    cudaGetSymbolAddress((void**)&csm,   g_csm);
    cudaGetSymbolAddress((void**)&um,    g_um);

    const int ZN = NROWS * DD;       // 4194304
    const int SN = NBT * DD;         // 65536
    const int AN = NN * NN;          // 4096
    float* Zfinal = (out_size >= ZN) ? out : Z;

    // --- setup ---
    adj_kernel<<<NN, NN>>>(A0, P, Qm, alpha, A);
    rowptr_kernel<<<1, 128>>>(srcI, E, rowptr);
    edge_kernel<<<(E + 127) / 128, 128>>>(srcI, dstI, A0, E, logA0);
    gemm(X, Wp, Z, NROWS, DD, DD, bp, nullptr, nullptr, 0);

    const int LN_BLOCKS = NROWS / 8;

    for (int l = 0; l < LL; l++) {
        const float* Wlin_l = Wlin + (size_t)l * DD * DD;
        const float* Wval_l = Wval + (size_t)l * DD * DD;
        const float* Wout_l = Wout + (size_t)l * DD * DD;
        const float* Wm1_l  = Wm1  + (size_t)l * DD * D4;
        const float* Wm2_l  = Wm2  + (size_t)l * D4 * DD;
        const float* l1g = ln1g + l * DD, *l1b = ln1b + l * DD;
        const float* l2g = ln2g + l * DD, *l2b = ln2b + l * DD;

        // fold LN gains into weights; colsum + bias vectors for the epilogue
        wprep_kernel<<<DD, DD>>>(Wlin_l, l1g, l1b, nullptr, DD, Wq, csq, uq);
        wprep_kernel<<<DD, DD>>>(Wval_l, l1g, l1b, nullptr, DD, Wv, csv, uv);
        wprep_kernel<<<D4, DD>>>(Wm1_l,  l2g, l2b, bm1 + l * D4, D4, Wm1p, csm, um);

        // LN1 stats on raw Z
        ln_stats_kernel<<<LN_BLOCKS, 256>>>(Z, mu1, rs1);

        // Xq = LN1(Z)@Wlin via epilogue trick (A operand = raw Z)
        gemm(Z, Wq, Xq, NROWS, DD, DD, nullptr, nullptr, nullptr, 0, mu1, rs1, csq, uq);
        gemm(Z, Wv, Xv, NROWS, DD, DD, nullptr, nullptr, nullptr, 0, mu1, rs1, csv, uv);
        hmix_kernel<<<NBT, 256>>>(A, Z, mu1, rs1, l1g, l1b, Hmix);

        dim3 ag(NN, NBT);
        attn_kernel<<<ag, 256>>>(Xq, Xv, a_att + l * HH * DHH, dstI, logA0, Y);

        // U = Y@Wout + Z + Hmix
        gemm(Y, Wout_l, U, NROWS, DD, DD, nullptr, Z, Hmix, 0);

        // gate in place; LN2 stats
        gate_kernel<<<LN_BLOCKS, 256>>>(U, g1w + l * DD, g1b + l * DD,
                                        g2w + l * DD, g2b + l, mu2, rs2);

        // MLP: M1 = silu(LN2(U)@Wm1 + bm1); Z = M1@Wm2 + bm2 + U
        float* Ztgt = (l == LL - 1) ? Zfinal : Z;
        gemm(U, Wm1p, M1, NROWS, DD, D4, nullptr, nullptr, nullptr, 1, mu2, rs2, csm, um);
        gemm(M1, Wm2_l, Ztgt, NROWS, D4, DD, bm2 + l * DD, U, nullptr, 0);
    }

    // --- outputs: [Zout | S | A] ---
    if (out_size >= ZN && Zfinal != out)
        copy_kernel<<<(ZN / 4 + 255) / 256, 256>>>(Z, out, ZN / 4);
    if (out_size >= ZN + SN)
        s_kernel<<<(SN + 255) / 256, 256>>>(Zfinal, out + ZN);
    if (out_size >= ZN + SN + AN)
        copy_kernel<<<(AN / 4 + 255) / 256, 256>>>(A, out + ZN + SN, AN / 4);
    int tail = out_size - (ZN + SN + AN);
    if (tail > 0)
        fill0_kernel<<<(tail + 255) / 256, 256>>>(out + ZN + SN + AN, tail);
}

// round 6
// speedup vs baseline: 1.1339x; 1.1339x over previous
#include <cuda_runtime.h>
#include <math.h>
#include <stdint.h>

// ---------------- problem constants ----------------
#define NBT 512            // B*T
#define NN 64
#define DD 128
#define HH 4
#define DHH 32
#define LL 3
#define D4 512
#define NROWS (NBT*NN)     // 32768
#define MAXE 4096

// ---------------- scratch (device globals; no allocation) ----------------
__device__ float g_Z    [NROWS*DD];
__device__ float g_Hmix [NROWS*DD];
__device__ float g_Xq   [NROWS*DD];
__device__ float g_Xv   [NROWS*DD];
__device__ float g_Y    [NROWS*DD];
__device__ float g_U    [NROWS*DD];
__device__ float g_M1   [NROWS*D4];
__device__ float g_A    [NN*NN];
__device__ float g_logA0[MAXE];
__device__ int   g_rowptr[NN+1];
__device__ float g_mu1  [NROWS];
__device__ float g_rs1  [NROWS];
__device__ float g_mu2  [NROWS];
__device__ float g_rs2  [NROWS];
// LN-folded weights + epilogue vectors
__device__ float g_Wq   [DD*DD];
__device__ float g_Wv   [DD*DD];
__device__ float g_Wm1p [DD*D4];
__device__ float g_csq[DD], g_uq[DD];
__device__ float g_csv[DD], g_uv[DD];
__device__ float g_csm[D4], g_um[D4];

// ---------------- bf16x3 tensor-core GEMM ----------------
// C = act( [LN-epi]( A@B ) + bias ) + add1 + add2
// LN-epi (if ecs): v = ers[r]*(acc - emu[r]*ecs[c]) + eu[c]   (bias folded in eu)
// Accuracy: x = hi(bf16) + lo(bf16); products al*bh + ah*bl + ah*bh (fp32 acc).
#define BM 128
#define BN 128
#define BKT 16
#define ASTP 12    // uint32 (bf16x2) stride per A row: 8 used + 4 pad -> conflict-free frags
#define BSTP 136   // uint32 stride per B k2-row: 128 used + 8 pad -> conflict-free frags

__device__ __forceinline__ void cp_async16(void* smem, const void* gmem) {
    unsigned sa = (unsigned)__cvta_generic_to_shared(smem);
    asm volatile("cp.async.cg.shared.global [%0], [%1], 16;\n" :: "r"(sa), "l"(gmem));
}
__device__ __forceinline__ uint32_t pack_bf16x2(float x0, float x1) {
    // low half = cvt(x0), high half = cvt(x1)
    uint32_t r;
    asm("cvt.rn.bf16x2.f32 %0, %1, %2;" : "=r"(r) : "f"(x1), "f"(x0));
    return r;
}
__device__ __forceinline__ void split_pair(float x0, float x1, uint32_t& h2, uint32_t& l2) {
    h2 = pack_bf16x2(x0, x1);
    float h0 = __uint_as_float(h2 << 16);
    float h1 = __uint_as_float(h2 & 0xffff0000u);
    l2 = pack_bf16x2(x0 - h0, x1 - h1);
}
__device__ __forceinline__ void mma_bf16(float* c, const uint32_t* a, const uint32_t* b) {
    asm volatile("mma.sync.aligned.m16n8k16.row.col.f32.bf16.bf16.f32 "
        "{%0,%1,%2,%3}, {%4,%5,%6,%7}, {%8,%9}, {%0,%1,%2,%3};"
        : "+f"(c[0]), "+f"(c[1]), "+f"(c[2]), "+f"(c[3])
        : "r"(a[0]), "r"(a[1]), "r"(a[2]), "r"(a[3]), "r"(b[0]), "r"(b[1]));
}

__global__ __launch_bounds__(256) void bfgemm_kernel(
    const float* __restrict__ A, const float* __restrict__ B, float* __restrict__ C,
    int M, int K, int N,
    const float* __restrict__ bias, const float* __restrict__ add1,
    const float* __restrict__ add2, int act,
    const float* __restrict__ emu, const float* __restrict__ ers,
    const float* __restrict__ ecs, const float* __restrict__ eu)
{
    __shared__ float rawA[BM * BKT];          // stride 16
    __shared__ float rawB[BKT * BN];          // stride 128
    __shared__ uint32_t Ahi[BM * ASTP], Alo[BM * ASTP];
    __shared__ uint32_t Bhi[(BKT/2) * BSTP], Blo[(BKT/2) * BSTP];

    const int tid  = threadIdx.x;
    const int lane = tid & 31;
    const int wid  = tid >> 5;
    const int wm = (wid & 1) * 64;
    const int wn = (wid >> 1) * 32;
    const int bm = blockIdx.y * BM;
    const int bn = blockIdx.x * BN;

    const float* Agp = A + (size_t)bm * K;
    const float* Bgp = B + bn;

    const int arow = tid >> 1;               // 0..127
    const int acol = (tid & 1) * 8;          // 0 or 8

    float c[4][4][4];
    #pragma unroll
    for (int mi = 0; mi < 4; mi++)
        #pragma unroll
        for (int ni = 0; ni < 4; ni++)
            #pragma unroll
            for (int q = 0; q < 4; q++) c[mi][ni][q] = 0.f;

    const int ntiles = K / BKT;

#define ISSUE_TILE(k0)                                                          \
    {                                                                           \
        cp_async16(&rawA[arow * 16 + acol],     Agp + (size_t)arow * K + (k0) + acol);     \
        cp_async16(&rawA[arow * 16 + acol + 4], Agp + (size_t)arow * K + (k0) + acol + 4); \
        _Pragma("unroll")                                                       \
        for (int i = 0; i < 2; i++) {                                           \
            int idx = tid * 2 + i;                                              \
            int bk = idx >> 5, bn4 = (idx & 31) * 4;                            \
            cp_async16(&rawB[bk * 128 + bn4], Bgp + (size_t)((k0) + bk) * N + bn4); \
        }                                                                       \
        asm volatile("cp.async.commit_group;\n");                               \
    }

    ISSUE_TILE(0);

    // conversion-thread mappings
    const int carow = tid >> 1;              // A: row 0..127
    const int ck2b  = (tid & 1) * 4;         // A: packed col base 0 or 4
    const int cbn   = tid & 127;             // B: column
    const int cbk2b = tid >> 7;              // B: packed row base 0 or 1 (then +2q)

    for (int t = 0; t < ntiles; t++) {
        asm volatile("cp.async.wait_group 0;\n");
        __syncthreads();

        // ---- convert raw fp32 -> packed bf16 hi/lo (each element once) ----
        {
            // A: this thread packs row carow, k = 2*ck2b .. 2*ck2b+7
            float4 x0 = *(const float4*)&rawA[carow * 16 + 2 * ck2b];
            float4 x1 = *(const float4*)&rawA[carow * 16 + 2 * ck2b + 4];
            uint32_t h, l;
            const int abase = carow * ASTP + ck2b;
            split_pair(x0.x, x0.y, h, l); Ahi[abase + 0] = h; Alo[abase + 0] = l;
            split_pair(x0.z, x0.w, h, l); Ahi[abase + 1] = h; Alo[abase + 1] = l;
            split_pair(x1.x, x1.y, h, l); Ahi[abase + 2] = h; Alo[abase + 2] = l;
            split_pair(x1.z, x1.w, h, l); Ahi[abase + 3] = h; Alo[abase + 3] = l;
            // B: this thread packs column cbn, k2 rows cbk2b, cbk2b+2, +4, +6
            #pragma unroll
            for (int q = 0; q < 4; q++) {
                const int k2 = cbk2b + 2 * q;
                float b0 = rawB[(2 * k2) * 128 + cbn];
                float b1 = rawB[(2 * k2 + 1) * 128 + cbn];
                split_pair(b0, b1, h, l);
                Bhi[k2 * BSTP + cbn] = h;
                Blo[k2 * BSTP + cbn] = l;
            }
        }
        __syncthreads();

        if (t + 1 < ntiles) ISSUE_TILE((t + 1) * BKT);

        // ---- fragments + mma (whole K=16 per mma) ----
        uint32_t ah[4][4], al[4][4], bh[4][2], bl[4][2];
        const int r0 = wm + (lane >> 2);
        const int k2 = lane & 3;
        #pragma unroll
        for (int mi = 0; mi < 4; mi++) {
            const int rb = (r0 + mi * 16) * ASTP;
            ah[mi][0] = Ahi[rb + k2];
            ah[mi][1] = Ahi[rb + 8 * ASTP + k2];
            ah[mi][2] = Ahi[rb + 4 + k2];
            ah[mi][3] = Ahi[rb + 8 * ASTP + 4 + k2];
            al[mi][0] = Alo[rb + k2];
            al[mi][1] = Alo[rb + 8 * ASTP + k2];
            al[mi][2] = Alo[rb + 4 + k2];
            al[mi][3] = Alo[rb + 8 * ASTP + 4 + k2];
        }
        const int bn0 = wn + (lane >> 2);
        #pragma unroll
        for (int ni = 0; ni < 4; ni++) {
            bh[ni][0] = Bhi[k2 * BSTP + bn0 + ni * 8];
            bh[ni][1] = Bhi[(k2 + 4) * BSTP + bn0 + ni * 8];
            bl[ni][0] = Blo[k2 * BSTP + bn0 + ni * 8];
            bl[ni][1] = Blo[(k2 + 4) * BSTP + bn0 + ni * 8];
        }
        #pragma unroll
        for (int mi = 0; mi < 4; mi++)
            #pragma unroll
            for (int ni = 0; ni < 4; ni++) {
                mma_bf16(c[mi][ni], al[mi], bh[ni]);
                mma_bf16(c[mi][ni], ah[mi], bl[ni]);
                mma_bf16(c[mi][ni], ah[mi], bh[ni]);
            }
        __syncthreads();
    }
#undef ISSUE_TILE

    // epilogue
    const bool lnepi = (ecs != nullptr);
    #pragma unroll
    for (int mi = 0; mi < 4; mi++) {
        const int r0 = bm + wm + mi * 16 + (lane >> 2);
        #pragma unroll
        for (int ni = 0; ni < 4; ni++) {
            const int cc = bn + wn + ni * 8 + 2 * (lane & 3);
            float b0 = 0.f, b1 = 0.f;
            if (bias) { b0 = bias[cc]; b1 = bias[cc + 1]; }
            float cs0 = 0.f, cs1 = 0.f, u0 = 0.f, u1 = 0.f;
            if (lnepi) { cs0 = ecs[cc]; cs1 = ecs[cc + 1]; u0 = eu[cc]; u1 = eu[cc + 1]; }
            #pragma unroll
            for (int half = 0; half < 2; half++) {
                const int r = r0 + half * 8;
                const size_t ro = (size_t)r * N + cc;
                float v0, v1;
                if (lnepi) {
                    float m = emu[r], s = ers[r];
                    v0 = s * (c[mi][ni][half * 2 + 0] - m * cs0) + u0;
                    v1 = s * (c[mi][ni][half * 2 + 1] - m * cs1) + u1;
                } else {
                    v0 = c[mi][ni][half * 2 + 0] + b0;
                    v1 = c[mi][ni][half * 2 + 1] + b1;
                }
                if (act) {
                    v0 = v0 / (1.0f + expf(-v0));
                    v1 = v1 / (1.0f + expf(-v1));
                }
                if (add1) { float2 a = *(const float2*)(add1 + ro); v0 += a.x; v1 += a.y; }
                if (add2) { float2 a = *(const float2*)(add2 + ro); v0 += a.x; v1 += a.y; }
                float2 o; o.x = v0; o.y = v1;
                *(float2*)(C + ro) = o;
            }
        }
    }
}

// ---------------- weight prep: W' = diag(g)W, cs = colsum(W'), u = b@W (+extra)
__global__ void wprep_kernel(const float* __restrict__ W, const float* __restrict__ g,
                             const float* __restrict__ b, const float* __restrict__ extra,
                             int N, float* __restrict__ Wp, float* __restrict__ cs,
                             float* __restrict__ u)
{
    const int n = blockIdx.x;      // column
    const int k = threadIdx.x;     // row (blockDim = 128 = DD)
    float w  = W[(size_t)k * N + n];
    float wp = g[k] * w;
    Wp[(size_t)k * N + n] = wp;
    float uu = b[k] * w;
    const int lane = k & 31, warp = k >> 5;
    #pragma unroll
    for (int o = 16; o; o >>= 1) {
        wp += __shfl_xor_sync(0xffffffffu, wp, o);
        uu += __shfl_xor_sync(0xffffffffu, uu, o);
    }
    __shared__ float scs[4], su[4];
    if (lane == 0) { scs[warp] = wp; su[warp] = uu; }
    __syncthreads();
    if (k == 0) {
        cs[n] = scs[0] + scs[1] + scs[2] + scs[3];
        float t = su[0] + su[1] + su[2] + su[3];
        u[n] = t + (extra ? extra[n] : 0.f);
    }
}

// ---------------- LN stats only (warp per row of 128) ----------------
__global__ void ln_stats_kernel(const float* __restrict__ X,
                                float* __restrict__ mu, float* __restrict__ rs)
{
    int r = blockIdx.x * (blockDim.x >> 5) + (threadIdx.x >> 5);
    if (r >= NROWS) return;
    int lane = threadIdx.x & 31;
    const float* x = X + (size_t)r * DD;
    float s = 0.f, ss = 0.f;
    #pragma unroll
    for (int q = 0; q < 4; q++) { float v = x[lane + 32*q]; s += v; ss += v*v; }
    #pragma unroll
    for (int o = 16; o; o >>= 1) {
        s  += __shfl_xor_sync(0xffffffffu, s,  o);
        ss += __shfl_xor_sync(0xffffffffu, ss, o);
    }
    float m   = s  * (1.f/128.f);
    float var = ss * (1.f/128.f) - m * m;
    if (lane == 0) { mu[r] = m; rs[r] = rsqrtf(var + 1e-5f); }
}

// ---------------- NodeGate: U <- U*g in place; emit LN2 stats ----------------
__global__ void gate_kernel(float* __restrict__ U,
    const float* __restrict__ g1w, const float* __restrict__ g1b,
    const float* __restrict__ g2w, const float* __restrict__ g2bp,
    float* __restrict__ mu2, float* __restrict__ rs2)
{
    int r = blockIdx.x * (blockDim.x >> 5) + (threadIdx.x >> 5);
    if (r >= NROWS) return;
    int lane = threadIdx.x & 31;
    float* u = U + (size_t)r * DD;
    float v[4], s = 0.f, ss = 0.f;
    #pragma unroll
    for (int q = 0; q < 4; q++) { v[q] = u[lane + 32*q]; s += v[q]; ss += v[q]*v[q]; }
    #pragma unroll
    for (int o = 16; o; o >>= 1) {
        s  += __shfl_xor_sync(0xffffffffu, s,  o);
        ss += __shfl_xor_sync(0xffffffffu, ss, o);
    }
    float m   = s  * (1.f/128.f);
    float var = ss * (1.f/128.f) - m * m;
    float acc = 0.f;
    #pragma unroll
    for (int q = 0; q < 4; q++) {
        int d = lane + 32*q;
        float t = m * g1w[d] + g1b[d];
        acc += (t / (1.f + expf(-t))) * g2w[d];
    }
    #pragma unroll
    for (int o = 16; o; o >>= 1) acc += __shfl_xor_sync(0xffffffffu, acc, o);
    float gate = 1.f / (1.f + expf(-(acc + g2bp[0])));
    #pragma unroll
    for (int q = 0; q < 4; q++) u[lane + 32*q] = v[q] * gate;
    if (lane == 0) {
        mu2[r] = m * gate;
        rs2[r] = rsqrtf(var * gate * gate + 1e-5f);
    }
}

// ---------------- Hmix = A @ LN1(Z)  (per bt; LN applied while staging) -------
__global__ __launch_bounds__(256) void hmix_kernel(const float* __restrict__ A,
    const float* __restrict__ Z,
    const float* __restrict__ mu, const float* __restrict__ rs,
    const float* __restrict__ lng, const float* __restrict__ lnb,
    float* __restrict__ Hmix)
{
    __shared__ float sA[NN*NN];
    __shared__ float sH[NN*DD];
    int bt = blockIdx.x;
    for (int t = threadIdx.x; t < NN*NN; t += blockDim.x) sA[t] = A[t];
    const float* Zb = Z + (size_t)bt * NN * DD;
    const int rbase = bt * NN;
    for (int t = threadIdx.x; t < NN*DD; t += blockDim.x) {
        int j = t >> 7, d = t & 127;
        sH[t] = (Zb[t] - mu[rbase + j]) * rs[rbase + j] * lng[d] + lnb[d];
    }
    __syncthreads();
    int d = threadIdx.x & 127;
    for (int i = threadIdx.x >> 7; i < NN; i += 2) {
        float acc = 0.f;
        #pragma unroll 8
        for (int j = 0; j < NN; j++) acc += sA[i*NN + j] * sH[j*DD + d];
        Hmix[((size_t)bt * NN + i) * DD + d] = acc;
    }
}

// ---------------- blended adjacency A ----------------
__global__ void adj_kernel(const float* __restrict__ A0, const float* __restrict__ P,
                           const float* __restrict__ Qm, const float* __restrict__ alphap,
                           float* __restrict__ A)
{
    int i = blockIdx.x, j = threadIdx.x;
    float a0 = A0[i*NN + j];
    float dot = 0.f;
    #pragma unroll
    for (int r = 0; r < 8; r++) dot += P[i*8 + r] * Qm[j*8 + r];
    float sp = (dot > 20.f) ? dot : log1pf(expf(dot));
    float ad = (a0 > 0.f) ? sp : 0.f;
    float a  = a0 * (1.f + alphap[0] * ad);
    __shared__ float sbuf[NN];
    sbuf[j] = a;
    __syncthreads();
    for (int st = 32; st >= 1; st >>= 1) {
        if (j < st) sbuf[j] += sbuf[j + st];
        __syncthreads();
    }
    A[i*NN + j] = a / (sbuf[0] + 1e-8f);
}

// ---------------- edge prep: CSR rowptr + logA0 ----------------
__global__ void rowptr_kernel(const int* __restrict__ src, int E, int* __restrict__ rowptr)
{
    int t = threadIdx.x;
    if (t > NN) return;
    int lo = 0, hi = E;
    while (lo < hi) { int mid = (lo + hi) >> 1; if (src[mid] < t) lo = mid + 1; else hi = mid; }
    rowptr[t] = lo;
}

__global__ void edge_kernel(const int* __restrict__ src, const int* __restrict__ dst,
                            const float* __restrict__ A0, int E, float* __restrict__ logA0)
{
    int e = blockIdx.x * blockDim.x + threadIdx.x;
    if (e < E) logA0[e] = logf(A0[src[e]*NN + dst[e]] + 1e-8f);
}

// ---------------- GATv2: block=(src node, bt); 2 warps per head split edges ---
__global__ __launch_bounds__(256) void attn_kernel(
    const float* __restrict__ Xq, const float* __restrict__ Xv,
    const float* __restrict__ a_att_l,
    const int* __restrict__ dstidx,
    const float* __restrict__ logA0, float* __restrict__ Y)
{
    const int i  = blockIdx.x;
    const int bt = blockIdx.y;
    const int wid  = threadIdx.x >> 5;
    const int lane = threadIdx.x & 31;
    const int h    = wid & 3;
    const int half = wid >> 2;

    __shared__ int   sdst[NN];
    __shared__ float slog[NN];
    __shared__ float sexp[HH][NN];
    __shared__ float sred[2][HH];
    __shared__ float syp[HH][32];

    const int e0 = g_rowptr[i];
    const int deg = g_rowptr[i + 1] - e0;
    for (int k = threadIdx.x; k < deg; k += blockDim.x) {
        sdst[k] = dstidx[e0 + k];
        slog[k] = logA0[e0 + k];
    }
    __syncthreads();

    const float a  = a_att_l[h * DHH + lane];
    const float qi = Xq[((size_t)bt * NN + i) * DD + h * DHH + lane];

    float vmax = -1e30f;
    for (int k = half; k < deg; k += 2) {
        int j = sdst[k];
        float x = qi + Xq[((size_t)bt * NN + j) * DD + h * DHH + lane];
        x = (x > 0.f) ? x : 0.2f * x;
        float v = x * a;
        #pragma unroll
        for (int o = 16; o; o >>= 1) v += __shfl_xor_sync(0xffffffffu, v, o);
        v += slog[k];
        sexp[h][k] = v;
        vmax = fmaxf(vmax, v);
    }
    if (lane == 0) sred[half][h] = vmax;
    __syncthreads();
    vmax = fmaxf(sred[0][h], sred[1][h]);
    __syncthreads();

    float den = 0.f;
    {
        int k = half * 32 + lane;
        if (k < deg) {
            float ev = expf(sexp[h][k] - vmax);
            sexp[h][k] = ev;
            den += ev;
        }
    }
    #pragma unroll
    for (int o = 16; o; o >>= 1) den += __shfl_xor_sync(0xffffffffu, den, o);
    __syncthreads();
    if (lane == 0) sred[half][h] = den;
    __syncthreads();
    const float inv = 1.f / (sred[0][h] + sred[1][h]);

    float y = 0.f;
    for (int k = half; k < deg; k += 2) {
        int j = sdst[k];
        y += sexp[h][k] * Xv[((size_t)bt * NN + j) * DD + h * DHH + lane];
    }
    if (half == 1) syp[h][lane] = y;
    __syncthreads();
    if (half == 0)
        Y[((size_t)bt * NN + i) * DD + h * DHH + lane] = (y + syp[h][lane]) * inv;
}

// ---------------- outputs ----------------
__global__ void copy_kernel(const float* __restrict__ src, float* __restrict__ dst, int n4)
{
    int i = blockIdx.x * blockDim.x + threadIdx.x;
    if (i < n4) ((float4*)dst)[i] = ((const float4*)src)[i];
}

__global__ void s_kernel(const float* __restrict__ Z, float* __restrict__ S)
{
    int idx = blockIdx.x * blockDim.x + threadIdx.x;
    if (idx >= NBT * DD) return;
    int bt = idx >> 7, d = idx & 127;
    float acc = 0.f;
    for (int n = 0; n < NN; n++) acc += Z[(((size_t)bt * NN) + n) * DD + d];
    S[idx] = acc * (1.f / (float)NN);
}

__global__ void fill0_kernel(float* __restrict__ p, int n)
{
    int i = blockIdx.x * blockDim.x + threadIdx.x;
    if (i < n) p[i] = 0.f;
}

// ---------------- host driver ----------------
static inline void gemm(const float* A, const float* B, float* C, int M, int K, int N,
                        const float* bias, const float* add1, const float* add2, int act,
                        const float* emu = nullptr, const float* ers = nullptr,
                        const float* ecs = nullptr, const float* eu = nullptr)
{
    dim3 g(N / BN, M / BM);
    bfgemm_kernel<<<g, 256>>>(A, B, C, M, K, N, bias, add1, add2, act,
                              emu, ers, ecs, eu);
}

extern "C" void kernel_launch(void* const* d_in, const int* in_sizes, int n_in,
                              void* d_out, int out_size)
{
    const float* X     = (const float*)d_in[0];
    const float* Wp    = (const float*)d_in[1];
    const float* bp    = (const float*)d_in[2];
    const float* P     = (const float*)d_in[3];
    const float* Qm    = (const float*)d_in[4];
    const float* alpha = (const float*)d_in[5];
    const float* ln1g  = (const float*)d_in[6];
    const float* ln1b  = (const float*)d_in[7];
    const float* Wlin  = (const float*)d_in[8];
    const float* Wval  = (const float*)d_in[9];
    const float* a_att = (const float*)d_in[10];
    const float* Wout  = (const float*)d_in[11];
    const float* g1w   = (const float*)d_in[12];
    const float* g1b   = (const float*)d_in[13];
    const float* g2w   = (const float*)d_in[14];
    const float* g2b   = (const float*)d_in[15];
    const float* ln2g  = (const float*)d_in[16];
    const float* ln2b  = (const float*)d_in[17];
    const float* Wm1   = (const float*)d_in[18];
    const float* bm1   = (const float*)d_in[19];
    const float* Wm2   = (const float*)d_in[20];
    const float* bm2   = (const float*)d_in[21];
    const float* A0    = (const float*)d_in[22];
    const int*   srcI  = (const int*)d_in[24];
    const int*   dstI  = (const int*)d_in[25];
    int E = in_sizes[24];
    float* out = (float*)d_out;

    float *Z, *Hmix, *Xq, *Xv, *Y, *U, *M1, *A, *logA0;
    float *mu1, *rs1, *mu2, *rs2;
    float *Wq, *Wv, *Wm1p, *csq, *uq, *csv, *uv, *csm, *um;
    int* rowptr;
    cudaGetSymbolAddress((void**)&Z,     g_Z);
    cudaGetSymbolAddress((void**)&Hmix,  g_Hmix);
    cudaGetSymbolAddress((void**)&Xq,    g_Xq);
    cudaGetSymbolAddress((void**)&Xv,    g_Xv);
    cudaGetSymbolAddress((void**)&Y,     g_Y);
    cudaGetSymbolAddress((void**)&U,     g_U);
    cudaGetSymbolAddress((void**)&M1,    g_M1);
    cudaGetSymbolAddress((void**)&A,     g_A);
    cudaGetSymbolAddress((void**)&logA0, g_logA0);
    cudaGetSymbolAddress((void**)&rowptr, g_rowptr);
    cudaGetSymbolAddress((void**)&mu1,   g_mu1);
    cudaGetSymbolAddress((void**)&rs1,   g_rs1);
    cudaGetSymbolAddress((void**)&mu2,   g_mu2);
    cudaGetSymbolAddress((void**)&rs2,   g_rs2);
    cudaGetSymbolAddress((void**)&Wq,    g_Wq);
    cudaGetSymbolAddress((void**)&Wv,    g_Wv);
    cudaGetSymbolAddress((void**)&Wm1p,  g_Wm1p);
    cudaGetSymbolAddress((void**)&csq,   g_csq);
    cudaGetSymbolAddress((void**)&uq,    g_uq);
    cudaGetSymbolAddress((void**)&csv,   g_csv);
    cudaGetSymbolAddress((void**)&uv,    g_uv);
    cudaGetSymbolAddress((void**)&csm,   g_csm);
    cudaGetSymbolAddress((void**)&um,    g_um);

    const int ZN = NROWS * DD;       // 4194304
    const int SN = NBT * DD;         // 65536
    const int AN = NN * NN;          // 4096
    float* Zfinal = (out_size >= ZN) ? out : Z;

    // --- setup ---
    adj_kernel<<<NN, NN>>>(A0, P, Qm, alpha, A);
    rowptr_kernel<<<1, 128>>>(srcI, E, rowptr);
    edge_kernel<<<(E + 127) / 128, 128>>>(srcI, dstI, A0, E, logA0);
    gemm(X, Wp, Z, NROWS, DD, DD, bp, nullptr, nullptr, 0);

    const int LN_BLOCKS = NROWS / 8;

    for (int l = 0; l < LL; l++) {
        const float* Wlin_l = Wlin + (size_t)l * DD * DD;
        const float* Wval_l = Wval + (size_t)l * DD * DD;
        const float* Wout_l = Wout + (size_t)l * DD * DD;
        const float* Wm1_l  = Wm1  + (size_t)l * DD * D4;
        const float* Wm2_l  = Wm2  + (size_t)l * D4 * DD;
        const float* l1g = ln1g + l * DD, *l1b = ln1b + l * DD;
        const float* l2g = ln2g + l * DD, *l2b = ln2b + l * DD;

        // fold LN gains into weights; colsum + bias vectors for the epilogue
        wprep_kernel<<<DD, DD>>>(Wlin_l, l1g, l1b, nullptr, DD, Wq, csq, uq);
        wprep_kernel<<<DD, DD>>>(Wval_l, l1g, l1b, nullptr, DD, Wv, csv, uv);
        wprep_kernel<<<D4, DD>>>(Wm1_l,  l2g, l2b, bm1 + l * D4, D4, Wm1p, csm, um);

        // LN1 stats on raw Z
        ln_stats_kernel<<<LN_BLOCKS, 256>>>(Z, mu1, rs1);

        // Xq = LN1(Z)@Wlin via epilogue trick (A operand = raw Z)
        gemm(Z, Wq, Xq, NROWS, DD, DD, nullptr, nullptr, nullptr, 0, mu1, rs1, csq, uq);
        gemm(Z, Wv, Xv, NROWS, DD, DD, nullptr, nullptr, nullptr, 0, mu1, rs1, csv, uv);
        hmix_kernel<<<NBT, 256>>>(A, Z, mu1, rs1, l1g, l1b, Hmix);

        dim3 ag(NN, NBT);
        attn_kernel<<<ag, 256>>>(Xq, Xv, a_att + l * HH * DHH, dstI, logA0, Y);

        // U = Y@Wout + Z + Hmix
        gemm(Y, Wout_l, U, NROWS, DD, DD, nullptr, Z, Hmix, 0);

        // gate in place; LN2 stats
        gate_kernel<<<LN_BLOCKS, 256>>>(U, g1w + l * DD, g1b + l * DD,
                                        g2w + l * DD, g2b + l, mu2, rs2);

        // MLP: M1 = silu(LN2(U)@Wm1 + bm1); Z = M1@Wm2 + bm2 + U
        float* Ztgt = (l == LL - 1) ? Zfinal : Z;
        gemm(U, Wm1p, M1, NROWS, DD, D4, nullptr, nullptr, nullptr, 1, mu2, rs2, csm, um);
        gemm(M1, Wm2_l, Ztgt, NROWS, D4, DD, bm2 + l * DD, U, nullptr, 0);
    }

    // --- outputs: [Zout | S | A] ---
    if (out_size >= ZN && Zfinal != out)
        copy_kernel<<<(ZN / 4 + 255) / 256, 256>>>(Z, out, ZN / 4);
    if (out_size >= ZN + SN)
        s_kernel<<<(SN + 255) / 256, 256>>>(Zfinal, out + ZN);
    if (out_size >= ZN + SN + AN)
        copy_kernel<<<(AN / 4 + 255) / 256, 256>>>(A, out + ZN + SN, AN / 4);
    int tail = out_size - (ZN + SN + AN);
    if (tail > 0)
        fill0_kernel<<<(tail + 255) / 256, 256>>>(out + ZN + SN + AN, tail);
}

// round 8
// speedup vs baseline: 1.2080x; 1.0653x over previous
#include <cuda_runtime.h>
#include <math.h>
#include <stdint.h>

// ---------------- problem constants ----------------
#define NBT 512            // B*T
#define NN 64
#define DD 128
#define HH 4
#define DHH 32
#define LL 3
#define D4 512
#define NROWS (NBT*NN)     // 32768
#define MAXE 4096

// ---------------- scratch (device globals; no allocation) ----------------
__device__ float g_Z    [NROWS*DD];
__device__ float g_Hmix [NROWS*DD];
__device__ float g_Xq   [NROWS*DD];
__device__ float g_Xv   [NROWS*DD];
__device__ float g_Y    [NROWS*DD];
__device__ float g_U    [NROWS*DD];
__device__ float g_M1   [NROWS*D4];
__device__ float g_A    [NN*NN];
__device__ float g_logA0[MAXE];
__device__ int   g_rowptr[NN+1];
__device__ float g_mu1  [NROWS];
__device__ float g_rs1  [NROWS];
__device__ float g_mu2  [NROWS];
__device__ float g_rs2  [NROWS];
// packed bf16 hi/lo weights (B operands), per-use buffers
__device__ uint32_t g_phQ [64*128],  g_plQ [64*128];
__device__ uint32_t g_phV [64*128],  g_plV [64*128];
__device__ uint32_t g_phO [64*128],  g_plO [64*128];
__device__ uint32_t g_phM1[64*512],  g_plM1[64*512];
__device__ uint32_t g_phM2[256*128], g_plM2[256*128];
// LN epilogue vectors
__device__ float g_csq[DD], g_uq[DD];
__device__ float g_csv[DD], g_uv[DD];
__device__ float g_csm[D4], g_um[D4];

// ---------------- helpers ----------------
__device__ __forceinline__ void cp_async16(void* smem, const void* gmem) {
    unsigned sa = (unsigned)__cvta_generic_to_shared(smem);
    asm volatile("cp.async.cg.shared.global [%0], [%1], 16;\n" :: "r"(sa), "l"(gmem));
}
__device__ __forceinline__ uint32_t pack_bf16x2(float x0, float x1) {
    uint32_t r;
    asm("cvt.rn.bf16x2.f32 %0, %1, %2;" : "=r"(r) : "f"(x1), "f"(x0));
    return r;
}
__device__ __forceinline__ void split_pair(float x0, float x1, uint32_t& h2, uint32_t& l2) {
    h2 = pack_bf16x2(x0, x1);
    float h0 = __uint_as_float(h2 << 16);
    float h1 = __uint_as_float(h2 & 0xffff0000u);
    l2 = pack_bf16x2(x0 - h0, x1 - h1);
}
__device__ __forceinline__ void mma_bf16(float* c, const uint32_t* a, const uint32_t* b) {
    asm volatile("mma.sync.aligned.m16n8k16.row.col.f32.bf16.bf16.f32 "
        "{%0,%1,%2,%3}, {%4,%5,%6,%7}, {%8,%9}, {%0,%1,%2,%3};"
        : "+f"(c[0]), "+f"(c[1]), "+f"(c[2]), "+f"(c[3])
        : "r"(a[0]), "r"(a[1]), "r"(a[2]), "r"(a[3]), "r"(b[0]), "r"(b[1]));
}

// ---------------- bf16x3 GEMM, B pre-packed, pipelined ----------------
// C = act( [LN-epi]( A@B ) + bias ) + add1 + add2
#define BM 128
#define BN 128
#define BKT 16
#define ASTP 12    // packed A row stride (u32): conflict-free fragment reads
#define BSTP 136   // packed B k2-row stride (u32): conflict-free fragment reads

__global__ __launch_bounds__(256) void bfgemm_kernel(
    const float* __restrict__ A, const uint32_t* __restrict__ Bh,
    const uint32_t* __restrict__ Bl, float* __restrict__ C,
    int M, int K, int N,
    const float* __restrict__ bias, const float* __restrict__ add1,
    const float* __restrict__ add2, int act,
    const float* __restrict__ emu, const float* __restrict__ ers,
    const float* __restrict__ ecs, const float* __restrict__ eu)
{
    __shared__ float    rawA[2][BM * BKT];       // 8KB x2
    __shared__ uint32_t pBh[2][8 * BSTP];        // 4.25KB x2
    __shared__ uint32_t pBl[2][8 * BSTP];        // 4.25KB x2
    __shared__ uint32_t Ahi[BM * ASTP];          // 6KB
    __shared__ uint32_t Alo[BM * ASTP];          // 6KB

    const int tid  = threadIdx.x;
    const int lane = tid & 31;
    const int wid  = tid >> 5;
    const int wm = (wid & 1) * 64;
    const int wn = (wid >> 1) * 32;
    const int bm = blockIdx.y * BM;
    const int bn = blockIdx.x * BN;

    const float*    Agp  = A  + (size_t)bm * K;
    const uint32_t* Bhgp = Bh + bn;
    const uint32_t* Blgp = Bl + bn;

    const int arow = tid >> 1;               // 0..127
    const int acol = (tid & 1) * 8;          // 0 or 8
    const int bk2  = tid >> 5;               // 0..7
    const int bc4  = (tid & 31) * 4;

    float c[4][4][4];
    #pragma unroll
    for (int mi = 0; mi < 4; mi++)
        #pragma unroll
        for (int ni = 0; ni < 4; ni++)
            #pragma unroll
            for (int q = 0; q < 4; q++) c[mi][ni][q] = 0.f;

    const int ntiles = K / BKT;

#define ISSUE_TILE(t)                                                              \
    {                                                                              \
        const int s_ = (t) & 1;                                                    \
        const int k0_ = (t) * BKT, k20_ = (t) * 8;                                 \
        cp_async16(&rawA[s_][arow * 16 + acol],     Agp + (size_t)arow * K + k0_ + acol);     \
        cp_async16(&rawA[s_][arow * 16 + acol + 4], Agp + (size_t)arow * K + k0_ + acol + 4); \
        cp_async16(&pBh[s_][bk2 * BSTP + bc4], Bhgp + (size_t)(k20_ + bk2) * N + bc4);        \
        cp_async16(&pBl[s_][bk2 * BSTP + bc4], Blgp + (size_t)(k20_ + bk2) * N + bc4);        \
        asm volatile("cp.async.commit_group;\n");                                  \
    }

    ISSUE_TILE(0);

    for (int t = 0; t < ntiles; t++) {
        const int s = t & 1;
        asm volatile("cp.async.wait_group 0;\n");   // loads(t) complete
        __syncthreads();                            // mma(t-1) done everywhere
        if (t + 1 < ntiles) ISSUE_TILE(t + 1);      // fills stage (t+1)&1

        // convert A raw fp32 -> packed bf16 hi/lo (8 elems/thread)
        {
            const int crow = tid >> 1;
            const int ck2  = (tid & 1) * 4;
            float4 x0 = *(const float4*)&rawA[s][crow * 16 + 2 * ck2];
            float4 x1 = *(const float4*)&rawA[s][crow * 16 + 2 * ck2 + 4];
            uint32_t h, l;
            const int ab = crow * ASTP + ck2;
            split_pair(x0.x, x0.y, h, l); Ahi[ab + 0] = h; Alo[ab + 0] = l;
            split_pair(x0.z, x0.w, h, l); Ahi[ab + 1] = h; Alo[ab + 1] = l;
            split_pair(x1.x, x1.y, h, l); Ahi[ab + 2] = h; Alo[ab + 2] = l;
            split_pair(x1.z, x1.w, h, l); Ahi[ab + 3] = h; Alo[ab + 3] = l;
        }
        __syncthreads();                            // Ahi/Alo ready

        // fragments + 48 mma
        uint32_t ah[4][4], al[4][4], bh[4][2], bl[4][2];
        const int r0 = wm + (lane >> 2);
        const int k2 = lane & 3;
        #pragma unroll
        for (int mi = 0; mi < 4; mi++) {
            const int rb = (r0 + mi * 16) * ASTP;
            ah[mi][0] = Ahi[rb + k2];
            ah[mi][1] = Ahi[rb + 8 * ASTP + k2];
            ah[mi][2] = Ahi[rb + 4 + k2];
            ah[mi][3] = Ahi[rb + 8 * ASTP + 4 + k2];
            al[mi][0] = Alo[rb + k2];
            al[mi][1] = Alo[rb + 8 * ASTP + k2];
            al[mi][2] = Alo[rb + 4 + k2];
            al[mi][3] = Alo[rb + 8 * ASTP + 4 + k2];
        }
        const int bn0 = wn + (lane >> 2);
        #pragma unroll
        for (int ni = 0; ni < 4; ni++) {
            bh[ni][0] = pBh[s][k2 * BSTP + bn0 + ni * 8];
            bh[ni][1] = pBh[s][(k2 + 4) * BSTP + bn0 + ni * 8];
            bl[ni][0] = pBl[s][k2 * BSTP + bn0 + ni * 8];
            bl[ni][1] = pBl[s][(k2 + 4) * BSTP + bn0 + ni * 8];
        }
        #pragma unroll
        for (int mi = 0; mi < 4; mi++)
            #pragma unroll
            for (int ni = 0; ni < 4; ni++) {
                mma_bf16(c[mi][ni], al[mi], bh[ni]);
                mma_bf16(c[mi][ni], ah[mi], bl[ni]);
                mma_bf16(c[mi][ni], ah[mi], bh[ni]);
            }
    }
#undef ISSUE_TILE

    // epilogue
    const bool lnepi = (ecs != nullptr);
    #pragma unroll
    for (int mi = 0; mi < 4; mi++) {
        const int r0 = bm + wm + mi * 16 + (lane >> 2);
        #pragma unroll
        for (int ni = 0; ni < 4; ni++) {
            const int cc = bn + wn + ni * 8 + 2 * (lane & 3);
            float b0 = 0.f, b1 = 0.f;
            if (bias) { b0 = bias[cc]; b1 = bias[cc + 1]; }
            float cs0 = 0.f, cs1 = 0.f, u0 = 0.f, u1 = 0.f;
            if (lnepi) { cs0 = ecs[cc]; cs1 = ecs[cc + 1]; u0 = eu[cc]; u1 = eu[cc + 1]; }
            #pragma unroll
            for (int half = 0; half < 2; half++) {
                const int r = r0 + half * 8;
                const size_t ro = (size_t)r * N + cc;
                float v0, v1;
                if (lnepi) {
                    float m = emu[r], sgn = ers[r];
                    v0 = sgn * (c[mi][ni][half * 2 + 0] - m * cs0) + u0;
                    v1 = sgn * (c[mi][ni][half * 2 + 1] - m * cs1) + u1;
                } else {
                    v0 = c[mi][ni][half * 2 + 0] + b0;
                    v1 = c[mi][ni][half * 2 + 1] + b1;
                }
                if (act) {
                    v0 = v0 / (1.0f + expf(-v0));
                    v1 = v1 / (1.0f + expf(-v1));
                }
                if (add1) { float2 a = *(const float2*)(add1 + ro); v0 += a.x; v1 += a.y; }
                if (add2) { float2 a = *(const float2*)(add2 + ro); v0 += a.x; v1 += a.y; }
                float2 o; o.x = v0; o.y = v1;
                *(float2*)(C + ro) = o;
            }
        }
    }
}

// ---------------- weight prep + pack: W'=diag(g)W -> bf16 hi/lo; cs, u ------
// grid = N columns, block = 64 threads (k2 pairs; K=128 rows)
__global__ void wprep_pack_kernel(const float* __restrict__ W, const float* __restrict__ g,
                                  const float* __restrict__ b, const float* __restrict__ extra,
                                  int N, uint32_t* __restrict__ ph, uint32_t* __restrict__ pl,
                                  float* __restrict__ cs, float* __restrict__ u)
{
    const int n = blockIdx.x;
    const int k2 = threadIdx.x;          // 0..63
    const int k0 = 2 * k2, k1 = k0 + 1;
    float w0 = W[(size_t)k0 * N + n], w1 = W[(size_t)k1 * N + n];
    float wp0 = g[k0] * w0, wp1 = g[k1] * w1;
    uint32_t h, l;
    split_pair(wp0, wp1, h, l);
    ph[(size_t)k2 * N + n] = h;
    pl[(size_t)k2 * N + n] = l;
    float s  = wp0 + wp1;
    float uu = b[k0] * w0 + b[k1] * w1;
    #pragma unroll
    for (int o = 16; o; o >>= 1) {
        s  += __shfl_xor_sync(0xffffffffu, s,  o);
        uu += __shfl_xor_sync(0xffffffffu, uu, o);
    }
    __shared__ float sh[4];
    if (threadIdx.x == 0)  { sh[0] = s; sh[1] = uu; }
    if (threadIdx.x == 32) { sh[2] = s; sh[3] = uu; }
    __syncthreads();
    if (threadIdx.x == 0) {
        cs[n] = sh[0] + sh[2];
        u[n]  = sh[1] + sh[3] + (extra ? extra[n] : 0.f);
    }
}

// plain pack: W[K,N] fp32 -> hi/lo packed [K/2, N]
__global__ void pack_kernel(const float* __restrict__ W, int K2N, int N,
                            uint32_t* __restrict__ ph, uint32_t* __restrict__ pl)
{
    int idx = blockIdx.x * blockDim.x + threadIdx.x;
    if (idx >= K2N) return;
    int k2 = idx / N, n = idx - k2 * N;
    float x0 = W[(size_t)(2 * k2) * N + n];
    float x1 = W[(size_t)(2 * k2 + 1) * N + n];
    uint32_t h, l;
    split_pair(x0, x1, h, l);
    ph[idx] = h; pl[idx] = l;
}

// ---------------- LN stats only (warp per row of 128) ----------------
__global__ void ln_stats_kernel(const float* __restrict__ X,
                                float* __restrict__ mu, float* __restrict__ rs)
{
    int r = blockIdx.x * (blockDim.x >> 5) + (threadIdx.x >> 5);
    if (r >= NROWS) return;
    int lane = threadIdx.x & 31;
    const float* x = X + (size_t)r * DD;
    float s = 0.f, ss = 0.f;
    #pragma unroll
    for (int q = 0; q < 4; q++) { float v = x[lane + 32*q]; s += v; ss += v*v; }
    #pragma unroll
    for (int o = 16; o; o >>= 1) {
        s  += __shfl_xor_sync(0xffffffffu, s,  o);
        ss += __shfl_xor_sync(0xffffffffu, ss, o);
    }
    float m   = s  * (1.f/128.f);
    float var = ss * (1.f/128.f) - m * m;
    if (lane == 0) { mu[r] = m; rs[r] = rsqrtf(var + 1e-5f); }
}

// ---------------- NodeGate: U <- U*g in place; emit LN2 stats ----------------
__global__ void gate_kernel(float* __restrict__ U,
    const float* __restrict__ g1w, const float* __restrict__ g1b,
    const float* __restrict__ g2w, const float* __restrict__ g2bp,
    float* __restrict__ mu2, float* __restrict__ rs2)
{
    int r = blockIdx.x * (blockDim.x >> 5) + (threadIdx.x >> 5);
    if (r >= NROWS) return;
    int lane = threadIdx.x & 31;
    float* u = U + (size_t)r * DD;
    float v[4], s = 0.f, ss = 0.f;
    #pragma unroll
    for (int q = 0; q < 4; q++) { v[q] = u[lane + 32*q]; s += v[q]; ss += v[q]*v[q]; }
    #pragma unroll
    for (int o = 16; o; o >>= 1) {
        s  += __shfl_xor_sync(0xffffffffu, s,  o);
        ss += __shfl_xor_sync(0xffffffffu, ss, o);
    }
    float m   = s  * (1.f/128.f);
    float var = ss * (1.f/128.f) - m * m;
    float acc = 0.f;
    #pragma unroll
    for (int q = 0; q < 4; q++) {
        int d = lane + 32*q;
        float t = m * g1w[d] + g1b[d];
        acc += (t / (1.f + expf(-t))) * g2w[d];
    }
    #pragma unroll
    for (int o = 16; o; o >>= 1) acc += __shfl_xor_sync(0xffffffffu, acc, o);
    float gate = 1.f / (1.f + expf(-(acc + g2bp[0])));
    #pragma unroll
    for (int q = 0; q < 4; q++) u[lane + 32*q] = v[q] * gate;
    if (lane == 0) {
        mu2[r] = m * gate;
        rs2[r] = rsqrtf(var * gate * gate + 1e-5f);
    }
}

// ---------------- Hmix = A @ LN1(Z) ----------------
__global__ __launch_bounds__(256) void hmix_kernel(const float* __restrict__ A,
    const float* __restrict__ Z,
    const float* __restrict__ mu, const float* __restrict__ rs,
    const float* __restrict__ lng, const float* __restrict__ lnb,
    float* __restrict__ Hmix)
{
    __shared__ float sA[NN*NN];
    __shared__ float sH[NN*DD];
    int bt = blockIdx.x;
    for (int t = threadIdx.x; t < NN*NN; t += blockDim.x) sA[t] = A[t];
    const float* Zb = Z + (size_t)bt * NN * DD;
    const int rbase = bt * NN;
    for (int t = threadIdx.x; t < NN*DD; t += blockDim.x) {
        int j = t >> 7, d = t & 127;
        sH[t] = (Zb[t] - mu[rbase + j]) * rs[rbase + j] * lng[d] + lnb[d];
    }
    __syncthreads();
    int d = threadIdx.x & 127;
    for (int i = threadIdx.x >> 7; i < NN; i += 2) {
        float acc = 0.f;
        #pragma unroll 8
        for (int j = 0; j < NN; j++) acc += sA[i*NN + j] * sH[j*DD + d];
        Hmix[((size_t)bt * NN + i) * DD + d] = acc;
    }
}

// ---------------- blended adjacency A ----------------
__global__ void adj_kernel(const float* __restrict__ A0, const float* __restrict__ P,
                           const float* __restrict__ Qm, const float* __restrict__ alphap,
                           float* __restrict__ A)
{
    int i = blockIdx.x, j = threadIdx.x;
    float a0 = A0[i*NN + j];
    float dot = 0.f;
    #pragma unroll
    for (int r = 0; r < 8; r++) dot += P[i*8 + r] * Qm[j*8 + r];
    float sp = (dot > 20.f) ? dot : log1pf(expf(dot));
    float ad = (a0 > 0.f) ? sp : 0.f;
    float a  = a0 * (1.f + alphap[0] * ad);
    __shared__ float sbuf[NN];
    sbuf[j] = a;
    __syncthreads();
    for (int st = 32; st >= 1; st >>= 1) {
        if (j < st) sbuf[j] += sbuf[j + st];
        __syncthreads();
    }
    A[i*NN + j] = a / (sbuf[0] + 1e-8f);
}

// ---------------- edge prep: CSR rowptr + logA0 ----------------
__global__ void rowptr_kernel(const int* __restrict__ src, int E, int* __restrict__ rowptr)
{
    int t = threadIdx.x;
    if (t > NN) return;
    int lo = 0, hi = E;
    while (lo < hi) { int mid = (lo + hi) >> 1; if (src[mid] < t) lo = mid + 1; else hi = mid; }
    rowptr[t] = lo;
}

__global__ void edge_kernel(const int* __restrict__ src, const int* __restrict__ dst,
                            const float* __restrict__ A0, int E, float* __restrict__ logA0)
{
    int e = blockIdx.x * blockDim.x + threadIdx.x;
    if (e < E) logA0[e] = logf(A0[src[e]*NN + dst[e]] + 1e-8f);
}

// ---------------- GATv2 v2: block = bt; warp owns (head, node); lane-per-edge
#define AST2 129   // padded smem row stride (floats) for sXq/sXv
__global__ __launch_bounds__(256) void attn_kernel(
    const float* __restrict__ Xq, const float* __restrict__ Xv,
    const float* __restrict__ a_att_l,
    const int* __restrict__ dstidx,
    const float* __restrict__ logA0, int E, float* __restrict__ Y)
{
    extern __shared__ float smem[];
    float* sXq  = smem;                        // NN*AST2
    float* sXv  = sXq + NN * AST2;             // NN*AST2
    float* slog = sXv + NN * AST2;             // MAXE
    int*   sdst = (int*)(slog + MAXE);         // MAXE
    float* sexp = (float*)(sdst + MAXE);       // 8*NN (per warp)
    float* sa   = sexp + 8 * NN;               // 128

    const int bt   = blockIdx.x;
    const int tid  = threadIdx.x;
    const int wid  = tid >> 5;
    const int lane = tid & 31;
    const int h    = wid & 3;
    const int half = wid >> 2;
    const size_t base = (size_t)bt * NN * DD;

    // stage Xq/Xv slab (padded), edges, attention vector
    for (int idx = tid; idx < NN * DD; idx += 256) {
        int r = idx >> 7, d = idx & 127;
        sXq[r * AST2 + d] = Xq[base + idx];
        sXv[r * AST2 + d] = Xv[base + idx];
    }
    for (int k = tid; k < E; k += 256) {
        sdst[k] = dstidx[k];
        slog[k] = logA0[k];
    }
    if (tid < HH * DHH) sa[tid] = a_att_l[tid];
    __syncthreads();

    float* myexp = sexp + wid * NN;

    for (int i = half; i < NN; i += 2) {       // warp owns whole node i, head h
        const int e0  = g_rowptr[i];
        const int deg = g_rowptr[i + 1] - e0;
        const float* qrow = &sXq[i * AST2 + h * DHH];

        // scores: lane-per-edge (dot over 32 dh serially, ILP-friendly)
        float vmax = -1e30f;
        for (int kb = 0; kb < deg; kb += 32) {
            const int k = kb + lane;
            const bool ok = (k < deg);
            const int j = ok ? sdst[e0 + k] : 0;
            const float* jrow = &sXq[j * AST2 + h * DHH];
            float acc = 0.f;
            #pragma unroll
            for (int d = 0; d < DHH; d++) {
                float x = qrow[d] + jrow[d];
                x = (x > 0.f) ? x : 0.2f * x;
                acc = fmaf(x, sa[h * DHH + d], acc);
            }
            float v = ok ? (acc + slog[e0 + k]) : -1e30f;
            if (ok) myexp[k] = v;
            vmax = fmaxf(vmax, v);
        }
        #pragma unroll
        for (int o = 16; o; o >>= 1) vmax = fmaxf(vmax, __shfl_xor_sync(0xffffffffu, vmax, o));
        __syncwarp();

        float den = 0.f;
        for (int kb = 0; kb < deg; kb += 32) {
            const int k = kb + lane;
            if (k < deg) {
                float ev = expf(myexp[k] - vmax);
                myexp[k] = ev;
                den += ev;
            }
        }
        #pragma unroll
        for (int o = 16; o; o >>= 1) den += __shfl_xor_sync(0xffffffffu, den, o);
        __syncwarp();
        const float inv = 1.f / den;

        // apply: lane = dh
        float y = 0.f;
        for (int k = 0; k < deg; k++) {
            const int j = sdst[e0 + k];
            y = fmaf(myexp[k], sXv[j * AST2 + h * DHH + lane], y);
        }
        Y[base + i * DD + h * DHH + lane] = y * inv;
        __syncwarp();
    }
}
#define ATTN_SMEM ((2 * NN * AST2 + 2 * MAXE + 8 * NN + 128) * 4)

// ---------------- outputs ----------------
__global__ void copy_kernel(const float* __restrict__ src, float* __restrict__ dst, int n4)
{
    int i = blockIdx.x * blockDim.x + threadIdx.x;
    if (i < n4) ((float4*)dst)[i] = ((const float4*)src)[i];
}

__global__ void s_kernel(const float* __restrict__ Z, float* __restrict__ S)
{
    int idx = blockIdx.x * blockDim.x + threadIdx.x;
    if (idx >= NBT * DD) return;
    int bt = idx >> 7, d = idx & 127;
    float acc = 0.f;
    for (int n = 0; n < NN; n++) acc += Z[(((size_t)bt * NN) + n) * DD + d];
    S[idx] = acc * (1.f / (float)NN);
}

__global__ void fill0_kernel(float* __restrict__ p, int n)
{
    int i = blockIdx.x * blockDim.x + threadIdx.x;
    if (i < n) p[i] = 0.f;
}

// ---------------- host driver ----------------
static inline void gemm(const float* A, const uint32_t* Bh, const uint32_t* Bl, float* C,
                        int M, int K, int N,
                        const float* bias, const float* add1, const float* add2, int act,
                        const float* emu = nullptr, const float* ers = nullptr,
                        const float* ecs = nullptr, const float* eu = nullptr)
{
    dim3 g(N / BN, M / BM);
    bfgemm_kernel<<<g, 256>>>(A, Bh, Bl, C, M, K, N, bias, add1, add2, act,
                              emu, ers, ecs, eu);
}

extern "C" void kernel_launch(void* const* d_in, const int* in_sizes, int n_in,
                              void* d_out, int out_size)
{
    const float* X     = (const float*)d_in[0];
    const float* Wp    = (const float*)d_in[1];
    const float* bp    = (const float*)d_in[2];
    const float* P     = (const float*)d_in[3];
    const float* Qm    = (const float*)d_in[4];
    const float* alpha = (const float*)d_in[5];
    const float* ln1g  = (const float*)d_in[6];
    const float* ln1b  = (const float*)d_in[7];
    const float* Wlin  = (const float*)d_in[8];
    const float* Wval  = (const float*)d_in[9];
    const float* a_att = (const float*)d_in[10];
    const float* Wout  = (const float*)d_in[11];
    const float* g1w   = (const float*)d_in[12];
    const float* g1b   = (const float*)d_in[13];
    const float* g2w   = (const float*)d_in[14];
    const float* g2b   = (const float*)d_in[15];
    const float* ln2g  = (const float*)d_in[16];
    const float* ln2b  = (const float*)d_in[17];
    const float* Wm1   = (const float*)d_in[18];
    const float* bm1   = (const float*)d_in[19];
    const float* Wm2   = (const float*)d_in[20];
    const float* bm2   = (const float*)d_in[21];
    const float* A0    = (const float*)d_in[22];
    const int*   srcI  = (const int*)d_in[24];
    const int*   dstI  = (const int*)d_in[25];
    int E = in_sizes[24];
    float* out = (float*)d_out;

    float *Z, *Hmix, *Xq, *Xv, *Y, *U, *M1, *A, *logA0;
    float *mu1, *rs1, *mu2, *rs2;
    float *csq, *uq, *csv, *uv, *csm, *um;
    uint32_t *phQ, *plQ, *phV, *plV, *phO, *plO, *phM1, *plM1, *phM2, *plM2;
    int* rowptr;
    cudaGetSymbolAddress((void**)&Z,     g_Z);
    cudaGetSymbolAddress((void**)&Hmix,  g_Hmix);
    cudaGetSymbolAddress((void**)&Xq,    g_Xq);
    cudaGetSymbolAddress((void**)&Xv,    g_Xv);
    cudaGetSymbolAddress((void**)&Y,     g_Y);
    cudaGetSymbolAddress((void**)&U,     g_U);
    cudaGetSymbolAddress((void**)&M1,    g_M1);
    cudaGetSymbolAddress((void**)&A,     g_A);
    cudaGetSymbolAddress((void**)&logA0, g_logA0);
    cudaGetSymbolAddress((void**)&rowptr, g_rowptr);
    cudaGetSymbolAddress((void**)&mu1,   g_mu1);
    cudaGetSymbolAddress((void**)&rs1,   g_rs1);
    cudaGetSymbolAddress((void**)&mu2,   g_mu2);
    cudaGetSymbolAddress((void**)&rs2,   g_rs2);
    cudaGetSymbolAddress((void**)&csq,   g_csq);
    cudaGetSymbolAddress((void**)&uq,    g_uq);
    cudaGetSymbolAddress((void**)&csv,   g_csv);
    cudaGetSymbolAddress((void**)&uv,    g_uv);
    cudaGetSymbolAddress((void**)&csm,   g_csm);
    cudaGetSymbolAddress((void**)&um,    g_um);
    cudaGetSymbolAddress((void**)&phQ,   g_phQ);
    cudaGetSymbolAddress((void**)&plQ,   g_plQ);
    cudaGetSymbolAddress((void**)&phV,   g_phV);
    cudaGetSymbolAddress((void**)&plV,   g_plV);
    cudaGetSymbolAddress((void**)&phO,   g_phO);
    cudaGetSymbolAddress((void**)&plO,   g_plO);
    cudaGetSymbolAddress((void**)&phM1,  g_phM1);
    cudaGetSymbolAddress((void**)&plM1,  g_plM1);
    cudaGetSymbolAddress((void**)&phM2,  g_phM2);
    cudaGetSymbolAddress((void**)&plM2,  g_plM2);

    cudaFuncSetAttribute(attn_kernel, cudaFuncAttributeMaxDynamicSharedMemorySize, ATTN_SMEM);

    const int ZN = NROWS * DD;       // 4194304
    const int SN = NBT * DD;         // 65536
    const int AN = NN * NN;          // 4096
    float* Zfinal = (out_size >= ZN) ? out : Z;

    // --- setup ---
    adj_kernel<<<NN, NN>>>(A0, P, Qm, alpha, A);
    rowptr_kernel<<<1, 128>>>(srcI, E, rowptr);
    edge_kernel<<<(E + 127) / 128, 128>>>(srcI, dstI, A0, E, logA0);
    pack_kernel<<<(64*128 + 255) / 256, 256>>>(Wp, 64*128, DD, phQ, plQ);
    gemm(X, phQ, plQ, Z, NROWS, DD, DD, bp, nullptr, nullptr, 0);

    const int LN_BLOCKS = NROWS / 8;

    for (int l = 0; l < LL; l++) {
        const float* Wlin_l = Wlin + (size_t)l * DD * DD;
        const float* Wval_l = Wval + (size_t)l * DD * DD;
        const float* Wout_l = Wout + (size_t)l * DD * DD;
        const float* Wm1_l  = Wm1  + (size_t)l * DD * D4;
        const float* Wm2_l  = Wm2  + (size_t)l * D4 * DD;
        const float* l1g = ln1g + l * DD, *l1b = ln1b + l * DD;
        const float* l2g = ln2g + l * DD, *l2b = ln2b + l * DD;

        // pack B operands (LN gains folded where applicable)
        wprep_pack_kernel<<<DD, 64>>>(Wlin_l, l1g, l1b, nullptr, DD, phQ, plQ, csq, uq);
        wprep_pack_kernel<<<DD, 64>>>(Wval_l, l1g, l1b, nullptr, DD, phV, plV, csv, uv);
        wprep_pack_kernel<<<D4, 64>>>(Wm1_l,  l2g, l2b, bm1 + l * D4, D4, phM1, plM1, csm, um);
        pack_kernel<<<(64*128 + 255) / 256, 256>>>(Wout_l, 64*128, DD, phO, plO);
        pack_kernel<<<(256*128 + 255) / 256, 256>>>(Wm2_l, 256*128, DD, phM2, plM2);

        // LN1 stats on raw Z; LN applied via epilogue trick / staging
        ln_stats_kernel<<<LN_BLOCKS, 256>>>(Z, mu1, rs1);

        gemm(Z, phQ, plQ, Xq, NROWS, DD, DD, nullptr, nullptr, nullptr, 0, mu1, rs1, csq, uq);
        gemm(Z, phV, plV, Xv, NROWS, DD, DD, nullptr, nullptr, nullptr, 0, mu1, rs1, csv, uv);
        hmix_kernel<<<NBT, 256>>>(A, Z, mu1, rs1, l1g, l1b, Hmix);

        attn_kernel<<<NBT, 256, ATTN_SMEM>>>(Xq, Xv, a_att + l * HH * DHH, dstI, logA0, E, Y);

        // U = Y@Wout + Z + Hmix
        gemm(Y, phO, plO, U, NROWS, DD, DD, nullptr, Z, Hmix, 0);

        // gate in place; LN2 stats
        gate_kernel<<<LN_BLOCKS, 256>>>(U, g1w + l * DD, g1b + l * DD,
                                        g2w + l * DD, g2b + l, mu2, rs2);

        // MLP: M1 = silu(LN2(U)@Wm1 + bm1); Z = M1@Wm2 + bm2 + U
        float* Ztgt = (l == LL - 1) ? Zfinal : Z;
        gemm(U, phM1, plM1, M1, NROWS, DD, D4, nullptr, nullptr, nullptr, 1, mu2, rs2, csm, um);
        gemm(M1, phM2, plM2, Ztgt, NROWS, D4, DD, bm2 + l * DD, U, nullptr, 0);
    }

    // --- outputs: [Zout | S | A] ---
    if (out_size >= ZN && Zfinal != out)
        copy_kernel<<<(ZN / 4 + 255) / 256, 256>>>(Z, out, ZN / 4);
    if (out_size >= ZN + SN)
        s_kernel<<<(SN + 255) / 256, 256>>>(Zfinal, out + ZN);
    if (out_size >= ZN + SN + AN)
        copy_kernel<<<(AN / 4 + 255) / 256, 256>>>(A, out + ZN + SN, AN / 4);
    int tail = out_size - (ZN + SN + AN);
    if (tail > 0)
        fill0_kernel<<<(tail + 255) / 256, 256>>>(out + ZN + SN + AN, tail);
}